// round 2
// baseline (speedup 1.0000x reference)
#include <cuda_runtime.h>
#include <cuda_bf16.h>

#define NUM_CLASSES 16384
#define FEAT_DIM    1024
#define ALPHA       0.5f
#define NSLOT       64
#define SLOT_STRIDE 16   // 16 doubles = 128 B between slots -> distinct LTS partitions

// Scratch (static device globals: zero-initialized at process start; the main
// kernel's last block restores them to zero at the end of every run, so each
// graph replay starts from a clean state without a dedicated zero kernel).
__device__ int          g_counts[NUM_CLASSES];
__device__ double       g_partial[NSLOT * SLOT_STRIDE];
__device__ unsigned int g_done;

// ---------------------------------------------------------------------------
// Kernel 1: bincount (g_counts is guaranteed zero at entry)
// ---------------------------------------------------------------------------
__global__ __launch_bounds__(256)
void bincount_kernel(const int* __restrict__ y_true) {
    int idx = blockIdx.x * blockDim.x + threadIdx.x;
    atomicAdd(&g_counts[y_true[idx]], 1);
}

// ---------------------------------------------------------------------------
// Kernel 2: fused main + finalize + scratch-reset
// One block per sample row. 256 threads x float4 = 1024 floats.
//   j  = y_true[i], jj = y_true[j]
//   d  = y_pred[i] - centers[j] + (ALPHA/(counts[jj]+1)) * (centers[jj] - y_pred[j])
//   loss = mean(d^2)
// ---------------------------------------------------------------------------
__global__ __launch_bounds__(256)
void centerloss_kernel(const int*   __restrict__ y_true,
                       const float* __restrict__ y_pred,
                       const float* __restrict__ centers,
                       float*       __restrict__ out) {
    const int row = blockIdx.x;
    const int tid = threadIdx.x;

    // scalar indices (broadcast loads)
    const int j  = y_true[row];
    const int jj = __ldg(&y_true[j]);
    const float scale = ALPHA / ((float)g_counts[jj] + 1.0f);

    const float4* yp_i = (const float4*)(y_pred  + (size_t)row * FEAT_DIM);
    const float4* c_j  = (const float4*)(centers + (size_t)j   * FEAT_DIM);
    const float4* c_jj = (const float4*)(centers + (size_t)jj  * FEAT_DIM);
    const float4* yp_j = (const float4*)(y_pred  + (size_t)j   * FEAT_DIM);

    // 256 threads * 4 floats = 1024 = FEAT_DIM (one float4 per thread),
    // 4 independent LDG.128 per thread -> good MLP
    float4 a = yp_i[tid];
    float4 b = c_j[tid];
    float4 c = c_jj[tid];
    float4 d = yp_j[tid];

    float dx = a.x - b.x + scale * (c.x - d.x);
    float dy = a.y - b.y + scale * (c.y - d.y);
    float dz = a.z - b.z + scale * (c.z - d.z);
    float dw = a.w - b.w + scale * (c.w - d.w);

    float s = dx*dx + dy*dy + dz*dz + dw*dw;

    // warp reduce
    #pragma unroll
    for (int off = 16; off > 0; off >>= 1)
        s += __shfl_xor_sync(0xFFFFFFFFu, s, off);

    __shared__ float warp_sums[8];
    __shared__ bool  s_last;
    const int wid = tid >> 5;
    const int lid = tid & 31;
    if (lid == 0) warp_sums[wid] = s;
    __syncthreads();

    if (tid == 0) {
        float v = 0.0f;
        #pragma unroll
        for (int w = 0; w < 8; w++) v += warp_sums[w];
        // 64 strided slots -> no single-address LTS serialization
        atomicAdd(&g_partial[(blockIdx.x & (NSLOT - 1)) * SLOT_STRIDE], (double)v);
        __threadfence();  // release: partial visible before ticket
        unsigned int ticket = atomicAdd(&g_done, 1u);
        s_last = (ticket == (unsigned int)(gridDim.x - 1));
    }
    __syncthreads();

    // ---- last block: finalize + reset scratch for the next graph replay ----
    if (s_last) {
        __threadfence();  // acquire: see all partials

        // parallel sum of 64 slots
        double dv = 0.0;
        if (tid < NSLOT) dv = g_partial[tid * SLOT_STRIDE];
        // reduce 64 values: shfl within 2 warps + smem combine
        #pragma unroll
        for (int off = 16; off > 0; off >>= 1)
            dv += __shfl_xor_sync(0xFFFFFFFFu, dv, off);
        __shared__ double dsum[2];
        if (tid < NSLOT && lid == 0) dsum[wid] = dv;
        __syncthreads();
        if (tid == 0) {
            double tot = dsum[0] + dsum[1];
            out[0] = (float)(tot / ((double)NUM_CLASSES * (double)FEAT_DIM));
        }

        // reset scratch: counts, partials, done counter
        for (int k = tid; k < NUM_CLASSES; k += 256) g_counts[k] = 0;
        for (int k = tid; k < NSLOT * SLOT_STRIDE; k += 256) g_partial[k] = 0.0;
        if (tid == 0) g_done = 0u;
    }
}

extern "C" void kernel_launch(void* const* d_in, const int* in_sizes, int n_in,
                              void* d_out, int out_size) {
    const int*   y_true  = (const int*)  d_in[0];
    const float* y_pred  = (const float*)d_in[1];
    const float* centers = (const float*)d_in[2];
    float* out = (float*)d_out;

    bincount_kernel<<<NUM_CLASSES / 256, 256>>>(y_true);
    centerloss_kernel<<<NUM_CLASSES, 256>>>(y_true, y_pred, centers, out);
}

// round 3
// speedup vs baseline: 1.5016x; 1.5016x over previous
#include <cuda_runtime.h>
#include <cuda_bf16.h>

#define NUM_CLASSES 16384
#define FEAT_DIM    1024
#define ALPHA       0.5f
#define NSLOT       64
#define SLOT_STRIDE 16   // 16 doubles = 128 B -> distinct LTS partitions

// Scratch (device globals: zero at process start; finalize_kernel restores
// them to zero each run, so every graph replay starts clean).
__device__ int    g_counts[NUM_CLASSES];
__device__ double g_partial[NSLOT * SLOT_STRIDE];

// ---------------------------------------------------------------------------
// Kernel 1: bincount (g_counts is zero at entry)
// ---------------------------------------------------------------------------
__global__ __launch_bounds__(256)
void bincount_kernel(const int* __restrict__ y_true) {
    int idx = blockIdx.x * blockDim.x + threadIdx.x;
    atomicAdd(&g_counts[y_true[idx]], 1);
}

// ---------------------------------------------------------------------------
// Kernel 2: main fused center-loss
// One block (128 threads) per sample row; each thread covers 2 float4 lanes
// of each of the 4 row-streams -> 8 independent LDG.128 in flight per thread.
//   j  = y_true[i], jj = y_true[j]
//   d  = y_pred[i] - centers[j] + (ALPHA/(counts[jj]+1)) * (centers[jj] - y_pred[j])
// ---------------------------------------------------------------------------
__global__ __launch_bounds__(128)
void centerloss_kernel(const int*   __restrict__ y_true,
                       const float* __restrict__ y_pred,
                       const float* __restrict__ centers) {
    const int row = blockIdx.x;
    const int tid = threadIdx.x;

    const int j  = y_true[row];
    const int jj = y_true[j];
    const float scale = ALPHA / ((float)g_counts[jj] + 1.0f);

    const float4* yp_i = (const float4*)(y_pred  + (size_t)row * FEAT_DIM);
    const float4* c_j  = (const float4*)(centers + (size_t)j   * FEAT_DIM);
    const float4* c_jj = (const float4*)(centers + (size_t)jj  * FEAT_DIM);
    const float4* yp_j = (const float4*)(y_pred  + (size_t)j   * FEAT_DIM);

    // 128 threads * 2 float4 = 256 float4 = 1024 floats
    const int t0 = tid;
    const int t1 = tid + 128;

    float4 a0 = yp_i[t0], a1 = yp_i[t1];
    float4 b0 = c_j[t0],  b1 = c_j[t1];
    float4 c0 = c_jj[t0], c1 = c_jj[t1];
    float4 d0 = yp_j[t0], d1 = yp_j[t1];

    float s = 0.0f;
    {
        float dx = a0.x - b0.x + scale * (c0.x - d0.x);
        float dy = a0.y - b0.y + scale * (c0.y - d0.y);
        float dz = a0.z - b0.z + scale * (c0.z - d0.z);
        float dw = a0.w - b0.w + scale * (c0.w - d0.w);
        s += dx*dx + dy*dy + dz*dz + dw*dw;
    }
    {
        float dx = a1.x - b1.x + scale * (c1.x - d1.x);
        float dy = a1.y - b1.y + scale * (c1.y - d1.y);
        float dz = a1.z - b1.z + scale * (c1.z - d1.z);
        float dw = a1.w - b1.w + scale * (c1.w - d1.w);
        s += dx*dx + dy*dy + dz*dz + dw*dw;
    }

    // warp reduce
    #pragma unroll
    for (int off = 16; off > 0; off >>= 1)
        s += __shfl_xor_sync(0xFFFFFFFFu, s, off);

    // block reduce (4 warps)
    __shared__ float warp_sums[4];
    const int wid = tid >> 5;
    const int lid = tid & 31;
    if (lid == 0) warp_sums[wid] = s;
    __syncthreads();

    if (tid == 0) {
        float v = warp_sums[0] + warp_sums[1] + warp_sums[2] + warp_sums[3];
        // 64 strided slots; ordering vs finalize guaranteed by kernel boundary
        atomicAdd(&g_partial[(row & (NSLOT - 1)) * SLOT_STRIDE], (double)v);
    }
}

// ---------------------------------------------------------------------------
// Kernel 3: finalize + scratch reset for next graph replay
//   block 0          : reduce 64 partial slots -> out, then zero partials
//   blocks 1..64     : zero g_counts (256 ints each, fully parallel)
// ---------------------------------------------------------------------------
__global__ __launch_bounds__(256)
void finalize_kernel(float* __restrict__ out) {
    const int tid = threadIdx.x;
    if (blockIdx.x == 0) {
        double dv = (tid < NSLOT) ? g_partial[tid * SLOT_STRIDE] : 0.0;
        #pragma unroll
        for (int off = 16; off > 0; off >>= 1)
            dv += __shfl_xor_sync(0xFFFFFFFFu, dv, off);
        __shared__ double dsum[2];
        const int wid = tid >> 5;
        const int lid = tid & 31;
        if (wid < 2 && lid == 0) dsum[wid] = dv;
        __syncthreads();
        if (tid == 0)
            out[0] = (float)((dsum[0] + dsum[1]) /
                             ((double)NUM_CLASSES * (double)FEAT_DIM));
        // reset partials
        if (tid < NSLOT) g_partial[tid * SLOT_STRIDE] = 0.0;
    } else {
        // blocks 1..64 zero g_counts: 64 blocks * 256 threads = 16384
        g_counts[(blockIdx.x - 1) * 256 + tid] = 0;
    }
}

extern "C" void kernel_launch(void* const* d_in, const int* in_sizes, int n_in,
                              void* d_out, int out_size) {
    const int*   y_true  = (const int*)  d_in[0];
    const float* y_pred  = (const float*)d_in[1];
    const float* centers = (const float*)d_in[2];
    float* out = (float*)d_out;

    bincount_kernel<<<NUM_CLASSES / 256, 256>>>(y_true);
    centerloss_kernel<<<NUM_CLASSES, 128>>>(y_true, y_pred, centers);
    finalize_kernel<<<1 + NUM_CLASSES / 256, 256>>>(out);
}